// round 9
// baseline (speedup 1.0000x reference)
#include <cuda_runtime.h>
#include <cstdint>

#define B_ 4
#define C_ 256
#define Q_ 256
#define XD_ 64
#define YD_ 32
#define E_ 64
#define H_ 128
#define ALPHA 0.1f

#define NTILES (B_ * C_ * 4)

typedef unsigned long long u64;

// U stored in fp16 B-fragment (m16n8k16) layout per (b,k): 32KB blocks.
__device__ uint32_t U_scratch[(size_t)B_ * C_ * C_ * E_ / 2];
__device__ float    P_scratch[(size_t)B_ * C_ * H_];

// ---------------- helpers (compute_80 features only) ----------
__device__ __forceinline__ uint32_t pack_h2(float lo, float hi) {
    uint32_t r;
    asm("cvt.rn.f16x2.f32 %0, %1, %2;" : "=r"(r) : "f"(hi), "f"(lo));
    return r;
}
__device__ __forceinline__ void mma_f16(float d[4], const uint32_t a[4], const uint32_t b[2]) {
    asm volatile(
        "mma.sync.aligned.m16n8k16.row.col.f32.f16.f16.f32 "
        "{%0,%1,%2,%3}, {%4,%5,%6,%7}, {%8,%9}, {%0,%1,%2,%3};"
        : "+f"(d[0]), "+f"(d[1]), "+f"(d[2]), "+f"(d[3])
        : "r"(a[0]), "r"(a[1]), "r"(a[2]), "r"(a[3]), "r"(b[0]), "r"(b[1]));
}
__device__ __forceinline__ uint32_t smem_u32(const void* p) {
    uint32_t a;
    asm("{ .reg .u64 t; cvta.to.shared.u64 t, %1; cvt.u32.u64 %0, t; }" : "=r"(a) : "l"(p));
    return a;
}
__device__ __forceinline__ void cp_async16(uint32_t s, const void* g) {
    asm volatile("cp.async.cg.shared.global [%0], [%1], 16;" :: "r"(s), "l"(g));
}
__device__ __forceinline__ void cp_commit() { asm volatile("cp.async.commit_group;" ::: "memory"); }
template <int N>
__device__ __forceinline__ void cp_wait() { asm volatile("cp.async.wait_group %0;" :: "n"(N) : "memory"); }

#define REGS 136
#define TILES 544

// ---------------------------------------------------------------------------
// Kernel 1: P[b,j,h] (fp32), 4 accumulation chains
// ---------------------------------------------------------------------------
__global__ void p_kernel(const float* __restrict__ x, const float* __restrict__ y,
                         const float* __restrict__ W1, const float* __restrict__ b1) {
    int bj = blockIdx.x;
    int h  = threadIdx.x;
    const float* xr = x + (size_t)bj * XD_;
    const float* yr = y + (size_t)bj * YD_;
    float a0 = b1[h], a1 = 0.f, a2 = 0.f, a3 = 0.f;
    #pragma unroll 4
    for (int d = 0; d < XD_; d += 4) {
        a0 = fmaf(xr[d],     W1[(d)     * H_ + h], a0);
        a1 = fmaf(xr[d + 1], W1[(d + 1) * H_ + h], a1);
        a2 = fmaf(xr[d + 2], W1[(d + 2) * H_ + h], a2);
        a3 = fmaf(xr[d + 3], W1[(d + 3) * H_ + h], a3);
    }
    #pragma unroll 4
    for (int d = 0; d < YD_; d += 4) {
        a0 = fmaf(yr[d],     W1[(XD_ + d)     * H_ + h], a0);
        a1 = fmaf(yr[d + 1], W1[(XD_ + d + 1) * H_ + h], a1);
        a2 = fmaf(yr[d + 2], W1[(XD_ + d + 2) * H_ + h], a2);
        a3 = fmaf(yr[d + 3], W1[(XD_ + d + 3) * H_ + h], a3);
    }
    P_scratch[(size_t)bj * H_ + h] = (a0 + a1) + (a2 + a3);
}

// ---------------------------------------------------------------------------
// Kernel 2: persistent fp16 tensor-core MLP (unchanged from R8 passing)
// ---------------------------------------------------------------------------
#define W1F 0
#define W2F 16384
#define W3F 49152
#define B2S 65536
#define B3S 66048
#define INF 66304
#define H1F 75008
#define H2F 92416
#define BOUNCE 66304
#define ROWB 144
#define MLP_SMEM_B 109824

__global__ void __launch_bounds__(256, 2)
mlp_tc_kernel(const float* __restrict__ rc,
              const float* __restrict__ W1,
              const float* __restrict__ b2v,
              const float* __restrict__ W2,
              const float* __restrict__ W3,
              const float* __restrict__ b3v) {
    extern __shared__ char smem[];
    const int t    = threadIdx.x;
    const int wid  = t >> 5;
    const int lane = t & 31;
    const int wm   = wid >> 2;
    const int wn   = wid & 3;

    for (int i = t; i < 4096; i += 256) {
        int r = i & 1, ln = (i >> 1) & 31, nt = (i >> 6) & 15, kt = i >> 10;
        int k = kt * 16 + (ln & 3) * 2 + r * 8;
        int n = nt * 8 + (ln >> 2);
        *(uint32_t*)(smem + W1F + i * 4) = pack_h2(W1[(96 + k) * H_ + n], W1[(96 + k + 1) * H_ + n]);
    }
    for (int i = t; i < 8192; i += 256) {
        int r = i & 1, ln = (i >> 1) & 31, nt = (i >> 6) & 15, kt = i >> 10;
        int k = kt * 16 + (ln & 3) * 2 + r * 8;
        int n = nt * 8 + (ln >> 2);
        *(uint32_t*)(smem + W2F + i * 4) = pack_h2(W2[(size_t)k * H_ + n], W2[(size_t)(k + 1) * H_ + n]);
    }
    for (int i = t; i < 4096; i += 256) {
        int r = i & 1, ln = (i >> 1) & 31, nt = (i >> 6) & 7, kt = i >> 9;
        int k = kt * 16 + (ln & 3) * 2 + r * 8;
        int n = nt * 8 + (ln >> 2);
        *(uint32_t*)(smem + W3F + i * 4) = pack_h2(W3[(size_t)k * E_ + n], W3[(size_t)(k + 1) * E_ + n]);
    }
    if (t < 128) *(float*)(smem + B2S + t * 4) = b2v[t];
    if (t < 64)  *(float*)(smem + B3S + t * 4) = b3v[t];
    __syncthreads();

    for (int tile = blockIdx.x; tile < NTILES; tile += gridDim.x) {
        const int jsub = tile & 3;
        const int bk   = tile >> 2;
        const int b    = bk >> 8;
        const int j0   = jsub * 64;

        {
            const float* rcin = rc + ((size_t)bk * C_ + j0) * E_;
            #pragma unroll
            for (int it = 0; it < 4; it++) {
                int idx = it * 256 + t;
                int r  = idx >> 4;
                int e0 = (idx & 15) * 4;
                float4 v = *(const float4*)&rcin[(size_t)r * E_ + e0];
                int mt = r >> 4, kt = e0 >> 4;
                int reg = ((r >> 3) & 1) | (((e0 >> 3) & 1) << 1);
                int lp  = (r & 7) * 4 + ((e0 & 7) >> 1);
                uint2 w;
                w.x = pack_h2(v.x, v.y);
                w.y = pack_h2(v.z, v.w);
                *(uint2*)(smem + INF + (mt * 4 + kt) * TILES + reg * REGS + lp * 4) = w;
            }
        }
        __syncthreads();

        // ---- Layer 1 ----
        {
            float d[2][4][4];
            const float* Pp = P_scratch + (size_t)(b * C_ + j0) * H_;
            #pragma unroll
            for (int mtl = 0; mtl < 2; mtl++) {
                int r0 = wm * 32 + mtl * 16 + (lane >> 2);
                #pragma unroll
                for (int ntl = 0; ntl < 4; ntl++) {
                    int col = wn * 32 + ntl * 8 + (lane & 3) * 2;
                    float2 p0 = *(const float2*)&Pp[(size_t)r0 * H_ + col];
                    float2 p1 = *(const float2*)&Pp[(size_t)(r0 + 8) * H_ + col];
                    d[mtl][ntl][0] = p0.x; d[mtl][ntl][1] = p0.y;
                    d[mtl][ntl][2] = p1.x; d[mtl][ntl][3] = p1.y;
                }
            }
            #pragma unroll
            for (int kt = 0; kt < 4; kt++) {
                uint32_t a[2][4];
                #pragma unroll
                for (int mtl = 0; mtl < 2; mtl++) {
                    const char* base = smem + INF + ((wm * 2 + mtl) * 4 + kt) * TILES + lane * 4;
                    a[mtl][0] = *(const uint32_t*)(base);
                    a[mtl][1] = *(const uint32_t*)(base + REGS);
                    a[mtl][2] = *(const uint32_t*)(base + 2 * REGS);
                    a[mtl][3] = *(const uint32_t*)(base + 3 * REGS);
                }
                #pragma unroll
                for (int ntl = 0; ntl < 4; ntl++) {
                    int nt = wn * 4 + ntl;
                    uint2 bv = *(const uint2*)(smem + W1F + ((kt * 16 + nt) * 32 + lane) * 8);
                    uint32_t bw[2] = {bv.x, bv.y};
                    #pragma unroll
                    for (int mtl = 0; mtl < 2; mtl++) mma_f16(d[mtl][ntl], a[mtl], bw);
                }
            }
            #pragma unroll
            for (int mtl = 0; mtl < 2; mtl++) {
                int mt2 = wm * 2 + mtl;
                int lp  = (lane >> 2) * 4 + (lane & 3);
                #pragma unroll
                for (int ntl = 0; ntl < 4; ntl++) {
                    int kt2 = wn * 2 + (ntl >> 1);
                    int rlo = (ntl & 1) * 2;
                    const char* fb = smem + H1F + (mt2 * 8 + kt2) * TILES + lp * 4;
                    *(uint32_t*)(fb + rlo * REGS) =
                        pack_h2(fmaxf(d[mtl][ntl][0], 0.0f), fmaxf(d[mtl][ntl][1], 0.0f));
                    *(uint32_t*)(fb + (rlo + 1) * REGS) =
                        pack_h2(fmaxf(d[mtl][ntl][2], 0.0f), fmaxf(d[mtl][ntl][3], 0.0f));
                }
            }
        }
        __syncthreads();

        // ---- Layer 2 ----
        {
            float d[2][4][4];
            #pragma unroll
            for (int mtl = 0; mtl < 2; mtl++)
                #pragma unroll
                for (int ntl = 0; ntl < 4; ntl++) {
                    int col = wn * 32 + ntl * 8 + (lane & 3) * 2;
                    float2 bb = *(const float2*)(smem + B2S + col * 4);
                    d[mtl][ntl][0] = bb.x; d[mtl][ntl][1] = bb.y;
                    d[mtl][ntl][2] = bb.x; d[mtl][ntl][3] = bb.y;
                }
            #pragma unroll
            for (int kt = 0; kt < 8; kt++) {
                uint32_t a[2][4];
                #pragma unroll
                for (int mtl = 0; mtl < 2; mtl++) {
                    const char* base = smem + H1F + ((wm * 2 + mtl) * 8 + kt) * TILES + lane * 4;
                    a[mtl][0] = *(const uint32_t*)(base);
                    a[mtl][1] = *(const uint32_t*)(base + REGS);
                    a[mtl][2] = *(const uint32_t*)(base + 2 * REGS);
                    a[mtl][3] = *(const uint32_t*)(base + 3 * REGS);
                }
                #pragma unroll
                for (int ntl = 0; ntl < 4; ntl++) {
                    int nt = wn * 4 + ntl;
                    uint2 bv = *(const uint2*)(smem + W2F + ((kt * 16 + nt) * 32 + lane) * 8);
                    uint32_t bw[2] = {bv.x, bv.y};
                    #pragma unroll
                    for (int mtl = 0; mtl < 2; mtl++) mma_f16(d[mtl][ntl], a[mtl], bw);
                }
            }
            #pragma unroll
            for (int mtl = 0; mtl < 2; mtl++) {
                int mt2 = wm * 2 + mtl;
                int lp  = (lane >> 2) * 4 + (lane & 3);
                #pragma unroll
                for (int ntl = 0; ntl < 4; ntl++) {
                    int kt2 = wn * 2 + (ntl >> 1);
                    int rlo = (ntl & 1) * 2;
                    const char* fb = smem + H2F + (mt2 * 8 + kt2) * TILES + lp * 4;
                    *(uint32_t*)(fb + rlo * REGS) =
                        pack_h2(fmaxf(d[mtl][ntl][0], 0.0f), fmaxf(d[mtl][ntl][1], 0.0f));
                    *(uint32_t*)(fb + (rlo + 1) * REGS) =
                        pack_h2(fmaxf(d[mtl][ntl][2], 0.0f), fmaxf(d[mtl][ntl][3], 0.0f));
                }
            }
        }
        __syncthreads();

        // ---- Layer 3 ----
        {
            float d[2][2][4];
            #pragma unroll
            for (int mtl = 0; mtl < 2; mtl++)
                #pragma unroll
                for (int ntl = 0; ntl < 2; ntl++) {
                    int e = wn * 16 + ntl * 8 + (lane & 3) * 2;
                    float2 bb = *(const float2*)(smem + B3S + e * 4);
                    d[mtl][ntl][0] = bb.x; d[mtl][ntl][1] = bb.y;
                    d[mtl][ntl][2] = bb.x; d[mtl][ntl][3] = bb.y;
                }
            #pragma unroll
            for (int kt = 0; kt < 8; kt++) {
                uint32_t a[2][4];
                #pragma unroll
                for (int mtl = 0; mtl < 2; mtl++) {
                    const char* base = smem + H2F + ((wm * 2 + mtl) * 8 + kt) * TILES + lane * 4;
                    a[mtl][0] = *(const uint32_t*)(base);
                    a[mtl][1] = *(const uint32_t*)(base + REGS);
                    a[mtl][2] = *(const uint32_t*)(base + 2 * REGS);
                    a[mtl][3] = *(const uint32_t*)(base + 3 * REGS);
                }
                #pragma unroll
                for (int ntl = 0; ntl < 2; ntl++) {
                    int nt = wn * 2 + ntl;
                    uint2 bv = *(const uint2*)(smem + W3F + ((kt * 8 + nt) * 32 + lane) * 8);
                    uint32_t bw[2] = {bv.x, bv.y};
                    #pragma unroll
                    for (int mtl = 0; mtl < 2; mtl++) mma_f16(d[mtl][ntl], a[mtl], bw);
                }
            }
            #pragma unroll
            for (int mtl = 0; mtl < 2; mtl++) {
                int row = wm * 32 + mtl * 16 + (lane >> 2);
                #pragma unroll
                for (int ntl = 0; ntl < 2; ntl++) {
                    int e = wn * 16 + ntl * 8 + (lane & 3) * 2;
                    *(uint32_t*)(smem + BOUNCE + row * ROWB + e * 2) =
                        pack_h2(d[mtl][ntl][0], d[mtl][ntl][1]);
                    *(uint32_t*)(smem + BOUNCE + (row + 8) * ROWB + e * 2) =
                        pack_h2(d[mtl][ntl][2], d[mtl][ntl][3]);
                }
            }
        }
        __syncthreads();

        {
            uint32_t* Ub = U_scratch + (size_t)bk * 8192;
            #pragma unroll
            for (int w = 0; w < 8; w++) {
                int idx = w * 256 + t;
                int r   = idx & 1;
                int ln  = (idx >> 1) & 31;
                int nt  = (idx >> 6) & 7;
                int ktl = (idx >> 9) & 3;
                int jl  = ktl * 16 + (ln & 3) * 2 + r * 8;
                int e   = nt * 8 + (ln >> 2);
                uint16_t h0 = *(const uint16_t*)(smem + BOUNCE + jl * ROWB + e * 2);
                uint16_t h1 = *(const uint16_t*)(smem + BOUNCE + (jl + 1) * ROWB + e * 2);
                uint32_t word = (uint32_t)h0 | ((uint32_t)h1 << 16);
                int ktg = (j0 >> 4) + ktl;
                Ub[((ktg * 8 + nt) * 32 + ln) * 2 + r] = word;
            }
        }
        __syncthreads();
    }
}

// ---------------------------------------------------------------------------
// Kernel 3: fp16 mma attention. A frags in REGISTERS (loaded once);
// B 4-buffer cp.async pipeline, 3 deep; 1 syncthreads per k.
// smem: B buffers 0..128K (4 x 32KB), A staging at 131072 (34816B)
// ---------------------------------------------------------------------------
#define ATB(i)    ((i) * 32768)
#define AT_ASTAGE 131072
#define AT_SMEM   165888

__global__ void __launch_bounds__(256)
attn_mma_kernel(const float* __restrict__ rc, const float* __restrict__ rq,
                const float* __restrict__ attc, const float* __restrict__ attq,
                float* __restrict__ out) {
    extern __shared__ char smem[];
    const uint32_t smem_base = smem_u32(smem);
    const int t = threadIdx.x;
    const int x = blockIdx.x;
    const int kg  = x & 15;
    const int Mq  = (x >> 4) & 3;
    const int map = (x >> 6) & 1;
    const int b   = x >> 7;

    const int wid  = t >> 5;
    const int lane = t & 31;
    const int wm = wid >> 2;
    const int wn = wid & 3;

    const int k0 = kg * 16;

    // ---- Prologue: launch B copies for k0..k2 ----
    #pragma unroll
    for (int pk = 0; pk < 3; pk++) {
        const char* src = (const char*)(U_scratch + ((size_t)(b * C_ + k0 + pk)) * 8192);
        #pragma unroll
        for (int it = 0; it < 8; it++) {
            int o = (it * 256 + t) * 16;
            cp_async16(smem_base + ATB(pk) + o, src + o);
        }
        cp_commit();
    }

    // ---- Stage A: 64 rows x 256 j, fp16 frag-major ----
    {
        const float* att = (map ? attq : attc) + (size_t)b * C_ * C_ + (size_t)(Mq * 64) * C_;
        #pragma unroll 4
        for (int it = 0; it < 16; it++) {
            int idx = it * 256 + t;
            int i  = idx >> 6;
            int j0 = (idx & 63) * 4;
            float4 v = *(const float4*)&att[(size_t)i * C_ + j0];
            int mt = i >> 4, kt = j0 >> 4;
            int reg = ((i >> 3) & 1) | (((j0 >> 3) & 1) << 1);
            int lp  = (i & 7) * 4 + ((j0 & 7) >> 1);
            uint2 w;
            w.x = pack_h2(v.x, v.y);
            w.y = pack_h2(v.z, v.w);
            *(uint2*)(smem + AT_ASTAGE + (mt * 16 + kt) * TILES + reg * REGS + lp * 4) = w;
        }
    }
    __syncthreads();

    // ---- Load A fragments to registers (this warp's 2 mt x 16 kt x 4) ----
    uint32_t areg[2][16][4];
    #pragma unroll
    for (int mtl = 0; mtl < 2; mtl++)
        #pragma unroll
        for (int kt = 0; kt < 16; kt++) {
            const char* base = smem + AT_ASTAGE + ((wm * 2 + mtl) * 16 + kt) * TILES + lane * 4;
            areg[mtl][kt][0] = *(const uint32_t*)(base);
            areg[mtl][kt][1] = *(const uint32_t*)(base + REGS);
            areg[mtl][kt][2] = *(const uint32_t*)(base + 2 * REGS);
            areg[mtl][kt][3] = *(const uint32_t*)(base + 3 * REGS);
        }

    float* outbase = out + (map ? (size_t)B_ * C_ * C_ * E_ : 0);
    const float* residbase = map ? rq : rc;

    #pragma unroll 1
    for (int kk = 0; kk < 16; kk++) {
        const int k = k0 + kk;

        // retire this k's B copy
        if (kk < 14)      cp_wait<2>();
        else if (kk == 14) cp_wait<1>();
        else               cp_wait<0>();
        __syncthreads();

        // issue copy for k+3 into the buffer freed at k-1
        if (kk + 3 < 16) {
            const char* src = (const char*)(U_scratch + ((size_t)(b * C_ + k + 3)) * 8192);
            uint32_t dst = smem_base + ATB((kk + 3) & 3);
            #pragma unroll
            for (int it = 0; it < 8; it++) {
                int o = (it * 256 + t) * 16;
                cp_async16(dst + o, src + o);
            }
            cp_commit();
        }

        const char* bbase = smem + ATB(kk & 3);

        // ---- mma mainloop: D[64x64] += A[64x256] * B[256x64], 16 kt ----
        float d[2][2][4];
        #pragma unroll
        for (int i0 = 0; i0 < 2; i0++)
            #pragma unroll
            for (int i1 = 0; i1 < 2; i1++)
                #pragma unroll
                for (int i2 = 0; i2 < 4; i2++) d[i0][i1][i2] = 0.0f;

        #pragma unroll
        for (int kt = 0; kt < 16; kt++) {
            uint32_t bw[2][2];
            #pragma unroll
            for (int ntl = 0; ntl < 2; ntl++) {
                int nt = wn * 2 + ntl;
                uint2 bv = *(const uint2*)(bbase + ((kt * 8 + nt) * 32 + lane) * 8);
                bw[ntl][0] = bv.x; bw[ntl][1] = bv.y;
            }
            #pragma unroll
            for (int mtl = 0; mtl < 2; mtl++)
                #pragma unroll
                for (int ntl = 0; ntl < 2; ntl++)
                    mma_f16(d[mtl][ntl], areg[mtl][kt], bw[ntl]);
        }

        // ---- epilogue: out = resid - ALPHA * D (fp32) ----
        {
            const float* resid = residbase + ((size_t)(b * C_ + k) * C_) * E_;
            float* o = outbase + ((size_t)(b * C_ + k) * C_) * E_;
            #pragma unroll
            for (int mtl = 0; mtl < 2; mtl++) {
                int row = Mq * 64 + wm * 32 + mtl * 16 + (lane >> 2);
                #pragma unroll
                for (int ntl = 0; ntl < 2; ntl++) {
                    int e = wn * 16 + ntl * 8 + (lane & 3) * 2;
                    float2 rA = *(const float2*)&resid[(size_t)row * E_ + e];
                    float2 rB = *(const float2*)&resid[(size_t)(row + 8) * E_ + e];
                    float2 oA, oB;
                    oA.x = rA.x - ALPHA * d[mtl][ntl][0];
                    oA.y = rA.y - ALPHA * d[mtl][ntl][1];
                    oB.x = rB.x - ALPHA * d[mtl][ntl][2];
                    oB.y = rB.y - ALPHA * d[mtl][ntl][3];
                    *(float2*)&o[(size_t)row * E_ + e]       = oA;
                    *(float2*)&o[(size_t)(row + 8) * E_ + e] = oB;
                }
            }
        }
    }
}

// ---------------------------------------------------------------------------
// Launch
// ---------------------------------------------------------------------------
extern "C" void kernel_launch(void* const* d_in, const int* in_sizes, int n_in,
                              void* d_out, int out_size) {
    const float* x    = (const float*)d_in[0];
    const float* y    = (const float*)d_in[1];
    const float* rc   = (const float*)d_in[2];
    const float* rq   = (const float*)d_in[3];
    const float* attc = (const float*)d_in[4];
    const float* attq = (const float*)d_in[5];
    const float* W1   = (const float*)d_in[6];
    const float* b1   = (const float*)d_in[7];
    const float* W2   = (const float*)d_in[8];
    const float* b2   = (const float*)d_in[9];
    const float* W3   = (const float*)d_in[10];
    const float* b3   = (const float*)d_in[11];
    float* out = (float*)d_out;

    cudaFuncSetAttribute(mlp_tc_kernel,   cudaFuncAttributeMaxDynamicSharedMemorySize, MLP_SMEM_B);
    cudaFuncSetAttribute(attn_mma_kernel, cudaFuncAttributeMaxDynamicSharedMemorySize, AT_SMEM);

    p_kernel<<<B_ * C_, H_>>>(x, y, W1, b1);
    mlp_tc_kernel<<<296, 256, MLP_SMEM_B>>>(rc, W1, b2, W2, W3, b3);
    attn_mma_kernel<<<512, 256, AT_SMEM>>>(rc, rq, attc, attq, out);
}

// round 10
// speedup vs baseline: 1.1353x; 1.1353x over previous
#include <cuda_runtime.h>
#include <cstdint>

#define B_ 4
#define C_ 256
#define Q_ 256
#define XD_ 64
#define YD_ 32
#define E_ 64
#define H_ 128
#define ALPHA 0.1f

#define NTILES (B_ * C_ * 4)

typedef unsigned long long u64;

// U stored in fp16 B-fragment (m16n8k16) layout per (b,k): 32KB blocks.
__device__ uint32_t U_scratch[(size_t)B_ * C_ * C_ * E_ / 2];
__device__ float    P_scratch[(size_t)B_ * C_ * H_];

// ---------------- helpers (compute_80 features only) ----------
__device__ __forceinline__ uint32_t pack_h2(float lo, float hi) {
    uint32_t r;
    asm("cvt.rn.f16x2.f32 %0, %1, %2;" : "=r"(r) : "f"(hi), "f"(lo));
    return r;
}
__device__ __forceinline__ void mma_f16(float d[4], const uint32_t a[4], const uint32_t b[2]) {
    asm volatile(
        "mma.sync.aligned.m16n8k16.row.col.f32.f16.f16.f32 "
        "{%0,%1,%2,%3}, {%4,%5,%6,%7}, {%8,%9}, {%0,%1,%2,%3};"
        : "+f"(d[0]), "+f"(d[1]), "+f"(d[2]), "+f"(d[3])
        : "r"(a[0]), "r"(a[1]), "r"(a[2]), "r"(a[3]), "r"(b[0]), "r"(b[1]));
}
__device__ __forceinline__ uint32_t smem_u32(const void* p) {
    uint32_t a;
    asm("{ .reg .u64 t; cvta.to.shared.u64 t, %1; cvt.u32.u64 %0, t; }" : "=r"(a) : "l"(p));
    return a;
}
__device__ __forceinline__ void cp_async16(uint32_t s, const void* g) {
    asm volatile("cp.async.cg.shared.global [%0], [%1], 16;" :: "r"(s), "l"(g));
}
__device__ __forceinline__ void cp_commit() { asm volatile("cp.async.commit_group;" ::: "memory"); }
__device__ __forceinline__ void cp_wait0()  { asm volatile("cp.async.wait_group 0;" ::: "memory"); }

#define REGS 136
#define TILES 544

// ---------------------------------------------------------------------------
// Kernel 1: P[b,j,h] (fp32) — simple version (measured fastest)
// ---------------------------------------------------------------------------
__global__ void p_kernel(const float* __restrict__ x, const float* __restrict__ y,
                         const float* __restrict__ W1, const float* __restrict__ b1) {
    int bj = blockIdx.x;
    int h  = threadIdx.x;
    const float* xr = x + (size_t)bj * XD_;
    const float* yr = y + (size_t)bj * YD_;
    float acc = b1[h];
    #pragma unroll 8
    for (int d = 0; d < XD_; d++) acc = fmaf(xr[d], W1[d * H_ + h], acc);
    #pragma unroll 8
    for (int d = 0; d < YD_; d++) acc = fmaf(yr[d], W1[(XD_ + d) * H_ + h], acc);
    P_scratch[(size_t)bj * H_ + h] = acc;
}

// ---------------------------------------------------------------------------
// Kernel 2: persistent fp16 tensor-core MLP.
// Bounce buffer lives in H1F (dead after layer 2) -> bounce->gmem drain
// overlaps next tile's input staging; 4 syncthreads per tile.
// ---------------------------------------------------------------------------
#define W1F 0
#define W2F 16384
#define W3F 49152
#define B2S 65536
#define B3S 66048
#define INF 66304
#define H1F 75008
#define H2F 92416
#define BOUNCE 75008          // = H1F (reused after layer 2 consumed it)
#define ROWB 144
#define MLP_SMEM_B 109824

__global__ void __launch_bounds__(256, 2)
mlp_tc_kernel(const float* __restrict__ rc,
              const float* __restrict__ W1,
              const float* __restrict__ b2v,
              const float* __restrict__ W2,
              const float* __restrict__ W3,
              const float* __restrict__ b3v) {
    extern __shared__ char smem[];
    const int t    = threadIdx.x;
    const int wid  = t >> 5;
    const int lane = t & 31;
    const int wm   = wid >> 2;
    const int wn   = wid & 3;

    for (int i = t; i < 4096; i += 256) {
        int r = i & 1, ln = (i >> 1) & 31, nt = (i >> 6) & 15, kt = i >> 10;
        int k = kt * 16 + (ln & 3) * 2 + r * 8;
        int n = nt * 8 + (ln >> 2);
        *(uint32_t*)(smem + W1F + i * 4) = pack_h2(W1[(96 + k) * H_ + n], W1[(96 + k + 1) * H_ + n]);
    }
    for (int i = t; i < 8192; i += 256) {
        int r = i & 1, ln = (i >> 1) & 31, nt = (i >> 6) & 15, kt = i >> 10;
        int k = kt * 16 + (ln & 3) * 2 + r * 8;
        int n = nt * 8 + (ln >> 2);
        *(uint32_t*)(smem + W2F + i * 4) = pack_h2(W2[(size_t)k * H_ + n], W2[(size_t)(k + 1) * H_ + n]);
    }
    for (int i = t; i < 4096; i += 256) {
        int r = i & 1, ln = (i >> 1) & 31, nt = (i >> 6) & 7, kt = i >> 9;
        int k = kt * 16 + (ln & 3) * 2 + r * 8;
        int n = nt * 8 + (ln >> 2);
        *(uint32_t*)(smem + W3F + i * 4) = pack_h2(W3[(size_t)k * E_ + n], W3[(size_t)(k + 1) * E_ + n]);
    }
    if (t < 128) *(float*)(smem + B2S + t * 4) = b2v[t];
    if (t < 64)  *(float*)(smem + B3S + t * 4) = b3v[t];

    int prev_bk = -1, prev_j0 = 0;    // bounce->gmem drain deferred to next iter

    for (int tile = blockIdx.x; tile < NTILES; tile += gridDim.x) {
        const int jsub = tile & 3;
        const int bk   = tile >> 2;
        const int b    = bk >> 8;
        const int j0   = jsub * 64;

        // ---- Phase X: drain previous tile's bounce to gmem + stage INF ----
        if (prev_bk >= 0) {
            uint32_t* Ub = U_scratch + (size_t)prev_bk * 8192;
            #pragma unroll
            for (int w = 0; w < 8; w++) {
                int idx = w * 256 + t;
                int r   = idx & 1;
                int ln  = (idx >> 1) & 31;
                int nt  = (idx >> 6) & 7;
                int ktl = (idx >> 9) & 3;
                int jl  = ktl * 16 + (ln & 3) * 2 + r * 8;
                int e   = nt * 8 + (ln >> 2);
                uint16_t h0 = *(const uint16_t*)(smem + BOUNCE + jl * ROWB + e * 2);
                uint16_t h1 = *(const uint16_t*)(smem + BOUNCE + (jl + 1) * ROWB + e * 2);
                uint32_t word = (uint32_t)h0 | ((uint32_t)h1 << 16);
                int ktg = (prev_j0 >> 4) + ktl;
                Ub[((ktg * 8 + nt) * 32 + ln) * 2 + r] = word;
            }
        }
        {
            const float* rcin = rc + ((size_t)bk * C_ + j0) * E_;
            #pragma unroll
            for (int it = 0; it < 4; it++) {
                int idx = it * 256 + t;
                int r  = idx >> 4;
                int e0 = (idx & 15) * 4;
                float4 v = *(const float4*)&rcin[(size_t)r * E_ + e0];
                int mt = r >> 4, kt = e0 >> 4;
                int reg = ((r >> 3) & 1) | (((e0 >> 3) & 1) << 1);
                int lp  = (r & 7) * 4 + ((e0 & 7) >> 1);
                uint2 w;
                w.x = pack_h2(v.x, v.y);
                w.y = pack_h2(v.z, v.w);
                *(uint2*)(smem + INF + (mt * 4 + kt) * TILES + reg * REGS + lp * 4) = w;
            }
        }
        __syncthreads();   // sync A: INF staged, bounce drained (and weights on iter 0)

        // ---- Layer 1: reads INF + P, writes H1F ----
        {
            float d[2][4][4];
            const float* Pp = P_scratch + (size_t)(b * C_ + j0) * H_;
            #pragma unroll
            for (int mtl = 0; mtl < 2; mtl++) {
                int r0 = wm * 32 + mtl * 16 + (lane >> 2);
                #pragma unroll
                for (int ntl = 0; ntl < 4; ntl++) {
                    int col = wn * 32 + ntl * 8 + (lane & 3) * 2;
                    float2 p0 = *(const float2*)&Pp[(size_t)r0 * H_ + col];
                    float2 p1 = *(const float2*)&Pp[(size_t)(r0 + 8) * H_ + col];
                    d[mtl][ntl][0] = p0.x; d[mtl][ntl][1] = p0.y;
                    d[mtl][ntl][2] = p1.x; d[mtl][ntl][3] = p1.y;
                }
            }
            #pragma unroll
            for (int kt = 0; kt < 4; kt++) {
                uint32_t a[2][4];
                #pragma unroll
                for (int mtl = 0; mtl < 2; mtl++) {
                    const char* base = smem + INF + ((wm * 2 + mtl) * 4 + kt) * TILES + lane * 4;
                    a[mtl][0] = *(const uint32_t*)(base);
                    a[mtl][1] = *(const uint32_t*)(base + REGS);
                    a[mtl][2] = *(const uint32_t*)(base + 2 * REGS);
                    a[mtl][3] = *(const uint32_t*)(base + 3 * REGS);
                }
                #pragma unroll
                for (int ntl = 0; ntl < 4; ntl++) {
                    int nt = wn * 4 + ntl;
                    uint2 bv = *(const uint2*)(smem + W1F + ((kt * 16 + nt) * 32 + lane) * 8);
                    uint32_t bw[2] = {bv.x, bv.y};
                    #pragma unroll
                    for (int mtl = 0; mtl < 2; mtl++) mma_f16(d[mtl][ntl], a[mtl], bw);
                }
            }
            #pragma unroll
            for (int mtl = 0; mtl < 2; mtl++) {
                int mt2 = wm * 2 + mtl;
                int lp  = (lane >> 2) * 4 + (lane & 3);
                #pragma unroll
                for (int ntl = 0; ntl < 4; ntl++) {
                    int kt2 = wn * 2 + (ntl >> 1);
                    int rlo = (ntl & 1) * 2;
                    const char* fb = smem + H1F + (mt2 * 8 + kt2) * TILES + lp * 4;
                    *(uint32_t*)(fb + rlo * REGS) =
                        pack_h2(fmaxf(d[mtl][ntl][0], 0.0f), fmaxf(d[mtl][ntl][1], 0.0f));
                    *(uint32_t*)(fb + (rlo + 1) * REGS) =
                        pack_h2(fmaxf(d[mtl][ntl][2], 0.0f), fmaxf(d[mtl][ntl][3], 0.0f));
                }
            }
        }
        __syncthreads();   // sync B

        // ---- Layer 2: reads H1F, writes H2F ----
        {
            float d[2][4][4];
            #pragma unroll
            for (int mtl = 0; mtl < 2; mtl++)
                #pragma unroll
                for (int ntl = 0; ntl < 4; ntl++) {
                    int col = wn * 32 + ntl * 8 + (lane & 3) * 2;
                    float2 bb = *(const float2*)(smem + B2S + col * 4);
                    d[mtl][ntl][0] = bb.x; d[mtl][ntl][1] = bb.y;
                    d[mtl][ntl][2] = bb.x; d[mtl][ntl][3] = bb.y;
                }
            #pragma unroll
            for (int kt = 0; kt < 8; kt++) {
                uint32_t a[2][4];
                #pragma unroll
                for (int mtl = 0; mtl < 2; mtl++) {
                    const char* base = smem + H1F + ((wm * 2 + mtl) * 8 + kt) * TILES + lane * 4;
                    a[mtl][0] = *(const uint32_t*)(base);
                    a[mtl][1] = *(const uint32_t*)(base + REGS);
                    a[mtl][2] = *(const uint32_t*)(base + 2 * REGS);
                    a[mtl][3] = *(const uint32_t*)(base + 3 * REGS);
                }
                #pragma unroll
                for (int ntl = 0; ntl < 4; ntl++) {
                    int nt = wn * 4 + ntl;
                    uint2 bv = *(const uint2*)(smem + W2F + ((kt * 16 + nt) * 32 + lane) * 8);
                    uint32_t bw[2] = {bv.x, bv.y};
                    #pragma unroll
                    for (int mtl = 0; mtl < 2; mtl++) mma_f16(d[mtl][ntl], a[mtl], bw);
                }
            }
            #pragma unroll
            for (int mtl = 0; mtl < 2; mtl++) {
                int mt2 = wm * 2 + mtl;
                int lp  = (lane >> 2) * 4 + (lane & 3);
                #pragma unroll
                for (int ntl = 0; ntl < 4; ntl++) {
                    int kt2 = wn * 2 + (ntl >> 1);
                    int rlo = (ntl & 1) * 2;
                    const char* fb = smem + H2F + (mt2 * 8 + kt2) * TILES + lp * 4;
                    *(uint32_t*)(fb + rlo * REGS) =
                        pack_h2(fmaxf(d[mtl][ntl][0], 0.0f), fmaxf(d[mtl][ntl][1], 0.0f));
                    *(uint32_t*)(fb + (rlo + 1) * REGS) =
                        pack_h2(fmaxf(d[mtl][ntl][2], 0.0f), fmaxf(d[mtl][ntl][3], 0.0f));
                }
            }
        }
        __syncthreads();   // sync C (H1F now dead -> becomes bounce)

        // ---- Layer 3: reads H2F, writes BOUNCE (=H1F) ----
        {
            float d[2][2][4];
            #pragma unroll
            for (int mtl = 0; mtl < 2; mtl++)
                #pragma unroll
                for (int ntl = 0; ntl < 2; ntl++) {
                    int e = wn * 16 + ntl * 8 + (lane & 3) * 2;
                    float2 bb = *(const float2*)(smem + B3S + e * 4);
                    d[mtl][ntl][0] = bb.x; d[mtl][ntl][1] = bb.y;
                    d[mtl][ntl][2] = bb.x; d[mtl][ntl][3] = bb.y;
                }
            #pragma unroll
            for (int kt = 0; kt < 8; kt++) {
                uint32_t a[2][4];
                #pragma unroll
                for (int mtl = 0; mtl < 2; mtl++) {
                    const char* base = smem + H2F + ((wm * 2 + mtl) * 8 + kt) * TILES + lane * 4;
                    a[mtl][0] = *(const uint32_t*)(base);
                    a[mtl][1] = *(const uint32_t*)(base + REGS);
                    a[mtl][2] = *(const uint32_t*)(base + 2 * REGS);
                    a[mtl][3] = *(const uint32_t*)(base + 3 * REGS);
                }
                #pragma unroll
                for (int ntl = 0; ntl < 2; ntl++) {
                    int nt = wn * 2 + ntl;
                    uint2 bv = *(const uint2*)(smem + W3F + ((kt * 8 + nt) * 32 + lane) * 8);
                    uint32_t bw[2] = {bv.x, bv.y};
                    #pragma unroll
                    for (int mtl = 0; mtl < 2; mtl++) mma_f16(d[mtl][ntl], a[mtl], bw);
                }
            }
            #pragma unroll
            for (int mtl = 0; mtl < 2; mtl++) {
                int row = wm * 32 + mtl * 16 + (lane >> 2);
                #pragma unroll
                for (int ntl = 0; ntl < 2; ntl++) {
                    int e = wn * 16 + ntl * 8 + (lane & 3) * 2;
                    *(uint32_t*)(smem + BOUNCE + row * ROWB + e * 2) =
                        pack_h2(d[mtl][ntl][0], d[mtl][ntl][1]);
                    *(uint32_t*)(smem + BOUNCE + (row + 8) * ROWB + e * 2) =
                        pack_h2(d[mtl][ntl][2], d[mtl][ntl][3]);
                }
            }
        }
        __syncthreads();   // sync D: bounce complete, drained next iteration

        prev_bk = bk; prev_j0 = j0;
    }

    // final drain
    if (prev_bk >= 0) {
        uint32_t* Ub = U_scratch + (size_t)prev_bk * 8192;
        #pragma unroll
        for (int w = 0; w < 8; w++) {
            int idx = w * 256 + t;
            int r   = idx & 1;
            int ln  = (idx >> 1) & 31;
            int nt  = (idx >> 6) & 7;
            int ktl = (idx >> 9) & 3;
            int jl  = ktl * 16 + (ln & 3) * 2 + r * 8;
            int e   = nt * 8 + (ln >> 2);
            uint16_t h0 = *(const uint16_t*)(smem + BOUNCE + jl * ROWB + e * 2);
            uint16_t h1 = *(const uint16_t*)(smem + BOUNCE + (jl + 1) * ROWB + e * 2);
            uint32_t word = (uint32_t)h0 | ((uint32_t)h1 << 16);
            int ktg = (prev_j0 >> 4) + ktl;
            Ub[((ktg * 8 + nt) * 32 + ln) * 2 + r] = word;
        }
    }
}

// ---------------------------------------------------------------------------
// Kernel 3: fp16 mma attention (R8 structure: A in smem, 2-buffer cp.async,
// 2 CTA/SM). k-groups of 8 (grid 1024) for better SM load balance.
// ---------------------------------------------------------------------------
#define AT_A  0
#define AT_B0 34816
#define AT_B1 67584
#define AT_SMEM 100352

__global__ void __launch_bounds__(256, 2)
attn_mma_kernel(const float* __restrict__ rc, const float* __restrict__ rq,
                const float* __restrict__ attc, const float* __restrict__ attq,
                float* __restrict__ out) {
    extern __shared__ char smem[];
    const uint32_t smem_base = smem_u32(smem);
    const int t = threadIdx.x;
    const int x = blockIdx.x;
    const int kg  = x & 31;            // 32 groups of 8 k
    const int Mq  = (x >> 5) & 3;
    const int map = (x >> 7) & 1;
    const int b   = x >> 8;

    const int wid  = t >> 5;
    const int lane = t & 31;
    const int wm = wid >> 2;
    const int wn = wid & 3;

    const int k0 = kg * 8;

    // ---- Kick off B stage for k0 into buf0 (async, 32KB) ----
    {
        const char* src = (const char*)(U_scratch + ((size_t)(b * C_ + k0)) * 8192);
        #pragma unroll
        for (int it = 0; it < 8; it++) {
            int o = (it * 256 + t) * 16;
            cp_async16(smem_base + AT_B0 + o, src + o);
        }
        cp_commit();
    }

    // ---- Stage A once: 64 rows x 256 j, fp16 frag-major ----
    {
        const float* att = (map ? attq : attc) + (size_t)b * C_ * C_ + (size_t)(Mq * 64) * C_;
        #pragma unroll 4
        for (int it = 0; it < 16; it++) {
            int idx = it * 256 + t;
            int i  = idx >> 6;
            int j0 = (idx & 63) * 4;
            float4 v = *(const float4*)&att[(size_t)i * C_ + j0];
            int mt = i >> 4, kt = j0 >> 4;
            int reg = ((i >> 3) & 1) | (((j0 >> 3) & 1) << 1);
            int lp  = (i & 7) * 4 + ((j0 & 7) >> 1);
            uint2 w;
            w.x = pack_h2(v.x, v.y);
            w.y = pack_h2(v.z, v.w);
            *(uint2*)(smem + AT_A + (mt * 16 + kt) * TILES + reg * REGS + lp * 4) = w;
        }
    }
    cp_wait0();
    __syncthreads();

    float* outbase = out + (map ? (size_t)B_ * C_ * C_ * E_ : 0);
    const float* residbase = map ? rq : rc;

    uint32_t bufoff = AT_B0;
    #pragma unroll 1
    for (int kk = 0; kk < 8; kk++) {
        const int k = k0 + kk;

        if (kk < 7) {
            const char* src = (const char*)(U_scratch + ((size_t)(b * C_ + k + 1)) * 8192);
            uint32_t dst = smem_base + (bufoff ^ (AT_B0 ^ AT_B1));
            #pragma unroll
            for (int it = 0; it < 8; it++) {
                int o = (it * 256 + t) * 16;
                cp_async16(dst + o, src + o);
            }
            cp_commit();
        }

        // ---- mma mainloop: D[64x64] += A[64x256] * B[256x64], 16 kt ----
        float d[2][2][4];
        #pragma unroll
        for (int i0 = 0; i0 < 2; i0++)
            #pragma unroll
            for (int i1 = 0; i1 < 2; i1++)
                #pragma unroll
                for (int i2 = 0; i2 < 4; i2++) d[i0][i1][i2] = 0.0f;

        #pragma unroll 4
        for (int kt = 0; kt < 16; kt++) {
            uint32_t a[2][4];
            #pragma unroll
            for (int mtl = 0; mtl < 2; mtl++) {
                const char* base = smem + AT_A + ((wm * 2 + mtl) * 16 + kt) * TILES + lane * 4;
                a[mtl][0] = *(const uint32_t*)(base);
                a[mtl][1] = *(const uint32_t*)(base + REGS);
                a[mtl][2] = *(const uint32_t*)(base + 2 * REGS);
                a[mtl][3] = *(const uint32_t*)(base + 3 * REGS);
            }
            uint32_t bw[2][2];
            #pragma unroll
            for (int ntl = 0; ntl < 2; ntl++) {
                int nt = wn * 2 + ntl;
                uint2 bv = *(const uint2*)(smem + bufoff + ((kt * 8 + nt) * 32 + lane) * 8);
                bw[ntl][0] = bv.x; bw[ntl][1] = bv.y;
            }
            #pragma unroll
            for (int mtl = 0; mtl < 2; mtl++)
                #pragma unroll
                for (int ntl = 0; ntl < 2; ntl++)
                    mma_f16(d[mtl][ntl], a[mtl], bw[ntl]);
        }

        // ---- epilogue: out = resid - ALPHA * D (fp32) ----
        {
            const float* resid = residbase + ((size_t)(b * C_ + k) * C_) * E_;
            float* o = outbase + ((size_t)(b * C_ + k) * C_) * E_;
            #pragma unroll
            for (int mtl = 0; mtl < 2; mtl++) {
                int row = Mq * 64 + wm * 32 + mtl * 16 + (lane >> 2);
                #pragma unroll
                for (int ntl = 0; ntl < 2; ntl++) {
                    int e = wn * 16 + ntl * 8 + (lane & 3) * 2;
                    float2 rA = *(const float2*)&resid[(size_t)row * E_ + e];
                    float2 rB = *(const float2*)&resid[(size_t)(row + 8) * E_ + e];
                    float2 oA, oB;
                    oA.x = rA.x - ALPHA * d[mtl][ntl][0];
                    oA.y = rA.y - ALPHA * d[mtl][ntl][1];
                    oB.x = rB.x - ALPHA * d[mtl][ntl][2];
                    oB.y = rB.y - ALPHA * d[mtl][ntl][3];
                    *(float2*)&o[(size_t)row * E_ + e]       = oA;
                    *(float2*)&o[(size_t)(row + 8) * E_ + e] = oB;
                }
            }
        }

        if (kk < 7) {
            cp_wait0();
            __syncthreads();
            bufoff ^= (AT_B0 ^ AT_B1);
        }
    }
}

// ---------------------------------------------------------------------------
// Launch
// ---------------------------------------------------------------------------
extern "C" void kernel_launch(void* const* d_in, const int* in_sizes, int n_in,
                              void* d_out, int out_size) {
    const float* x    = (const float*)d_in[0];
    const float* y    = (const float*)d_in[1];
    const float* rc   = (const float*)d_in[2];
    const float* rq   = (const float*)d_in[3];
    const float* attc = (const float*)d_in[4];
    const float* attq = (const float*)d_in[5];
    const float* W1   = (const float*)d_in[6];
    const float* b1   = (const float*)d_in[7];
    const float* W2   = (const float*)d_in[8];
    const float* b2   = (const float*)d_in[9];
    const float* W3   = (const float*)d_in[10];
    const float* b3   = (const float*)d_in[11];
    float* out = (float*)d_out;

    cudaFuncSetAttribute(mlp_tc_kernel,   cudaFuncAttributeMaxDynamicSharedMemorySize, MLP_SMEM_B);
    cudaFuncSetAttribute(attn_mma_kernel, cudaFuncAttributeMaxDynamicSharedMemorySize, AT_SMEM);

    p_kernel<<<B_ * C_, H_>>>(x, y, W1, b1);
    mlp_tc_kernel<<<296, 256, MLP_SMEM_B>>>(rc, W1, b2, W2, W3, b3);
    attn_mma_kernel<<<1024, 256, AT_SMEM>>>(rc, rq, attc, attq, out);
}

// round 11
// speedup vs baseline: 1.1434x; 1.0072x over previous
#include <cuda_runtime.h>
#include <cstdint>

#define B_ 4
#define C_ 256
#define Q_ 256
#define XD_ 64
#define YD_ 32
#define E_ 64
#define H_ 128
#define ALPHA 0.1f

#define NTILES (B_ * C_ * 4)

typedef unsigned long long u64;

// U stored in fp16 B-fragment (m16n8k16) layout per (b,k): 32KB blocks.
__device__ uint32_t U_scratch[(size_t)B_ * C_ * C_ * E_ / 2];
__device__ float    P_scratch[(size_t)B_ * C_ * H_];

// ---------------- helpers (compute_80 features only) ----------
__device__ __forceinline__ uint32_t pack_h2(float lo, float hi) {
    uint32_t r;
    asm("cvt.rn.f16x2.f32 %0, %1, %2;" : "=r"(r) : "f"(hi), "f"(lo));
    return r;
}
__device__ __forceinline__ void mma_f16(float d[4], const uint32_t a[4], const uint32_t b[2]) {
    asm volatile(
        "mma.sync.aligned.m16n8k16.row.col.f32.f16.f16.f32 "
        "{%0,%1,%2,%3}, {%4,%5,%6,%7}, {%8,%9}, {%0,%1,%2,%3};"
        : "+f"(d[0]), "+f"(d[1]), "+f"(d[2]), "+f"(d[3])
        : "r"(a[0]), "r"(a[1]), "r"(a[2]), "r"(a[3]), "r"(b[0]), "r"(b[1]));
}
__device__ __forceinline__ uint32_t smem_u32(const void* p) {
    uint32_t a;
    asm("{ .reg .u64 t; cvta.to.shared.u64 t, %1; cvt.u32.u64 %0, t; }" : "=r"(a) : "l"(p));
    return a;
}
__device__ __forceinline__ void cp_async16(uint32_t s, const void* g) {
    asm volatile("cp.async.cg.shared.global [%0], [%1], 16;" :: "r"(s), "l"(g));
}
__device__ __forceinline__ void cp_commit() { asm volatile("cp.async.commit_group;" ::: "memory"); }
__device__ __forceinline__ void cp_wait0()  { asm volatile("cp.async.wait_group 0;" ::: "memory"); }

#define REGS 136
#define TILES 544

// ---------------------------------------------------------------------------
// Kernel 1: P[b,j,h] (fp32) — simple version (measured fastest)
// ---------------------------------------------------------------------------
__global__ void p_kernel(const float* __restrict__ x, const float* __restrict__ y,
                         const float* __restrict__ W1, const float* __restrict__ b1) {
    int bj = blockIdx.x;
    int h  = threadIdx.x;
    const float* xr = x + (size_t)bj * XD_;
    const float* yr = y + (size_t)bj * YD_;
    float acc = b1[h];
    #pragma unroll 8
    for (int d = 0; d < XD_; d++) acc = fmaf(xr[d], W1[d * H_ + h], acc);
    #pragma unroll 8
    for (int d = 0; d < YD_; d++) acc = fmaf(yr[d], W1[(XD_ + d) * H_ + h], acc);
    P_scratch[(size_t)bj * H_ + h] = acc;
}

// ---------------------------------------------------------------------------
// Kernel 2: persistent fp16 tensor-core MLP (unchanged from R10 passing)
// ---------------------------------------------------------------------------
#define W1F 0
#define W2F 16384
#define W3F 49152
#define B2S 65536
#define B3S 66048
#define INF 66304
#define H1F 75008
#define H2F 92416
#define BOUNCE 75008
#define ROWB 144
#define MLP_SMEM_B 109824

__global__ void __launch_bounds__(256, 2)
mlp_tc_kernel(const float* __restrict__ rc,
              const float* __restrict__ W1,
              const float* __restrict__ b2v,
              const float* __restrict__ W2,
              const float* __restrict__ W3,
              const float* __restrict__ b3v) {
    extern __shared__ char smem[];
    const int t    = threadIdx.x;
    const int wid  = t >> 5;
    const int lane = t & 31;
    const int wm   = wid >> 2;
    const int wn   = wid & 3;

    for (int i = t; i < 4096; i += 256) {
        int r = i & 1, ln = (i >> 1) & 31, nt = (i >> 6) & 15, kt = i >> 10;
        int k = kt * 16 + (ln & 3) * 2 + r * 8;
        int n = nt * 8 + (ln >> 2);
        *(uint32_t*)(smem + W1F + i * 4) = pack_h2(W1[(96 + k) * H_ + n], W1[(96 + k + 1) * H_ + n]);
    }
    for (int i = t; i < 8192; i += 256) {
        int r = i & 1, ln = (i >> 1) & 31, nt = (i >> 6) & 15, kt = i >> 10;
        int k = kt * 16 + (ln & 3) * 2 + r * 8;
        int n = nt * 8 + (ln >> 2);
        *(uint32_t*)(smem + W2F + i * 4) = pack_h2(W2[(size_t)k * H_ + n], W2[(size_t)(k + 1) * H_ + n]);
    }
    for (int i = t; i < 4096; i += 256) {
        int r = i & 1, ln = (i >> 1) & 31, nt = (i >> 6) & 7, kt = i >> 9;
        int k = kt * 16 + (ln & 3) * 2 + r * 8;
        int n = nt * 8 + (ln >> 2);
        *(uint32_t*)(smem + W3F + i * 4) = pack_h2(W3[(size_t)k * E_ + n], W3[(size_t)(k + 1) * E_ + n]);
    }
    if (t < 128) *(float*)(smem + B2S + t * 4) = b2v[t];
    if (t < 64)  *(float*)(smem + B3S + t * 4) = b3v[t];

    int prev_bk = -1, prev_j0 = 0;

    for (int tile = blockIdx.x; tile < NTILES; tile += gridDim.x) {
        const int jsub = tile & 3;
        const int bk   = tile >> 2;
        const int b    = bk >> 8;
        const int j0   = jsub * 64;

        if (prev_bk >= 0) {
            uint32_t* Ub = U_scratch + (size_t)prev_bk * 8192;
            #pragma unroll
            for (int w = 0; w < 8; w++) {
                int idx = w * 256 + t;
                int r   = idx & 1;
                int ln  = (idx >> 1) & 31;
                int nt  = (idx >> 6) & 7;
                int ktl = (idx >> 9) & 3;
                int jl  = ktl * 16 + (ln & 3) * 2 + r * 8;
                int e   = nt * 8 + (ln >> 2);
                uint16_t h0 = *(const uint16_t*)(smem + BOUNCE + jl * ROWB + e * 2);
                uint16_t h1 = *(const uint16_t*)(smem + BOUNCE + (jl + 1) * ROWB + e * 2);
                uint32_t word = (uint32_t)h0 | ((uint32_t)h1 << 16);
                int ktg = (prev_j0 >> 4) + ktl;
                Ub[((ktg * 8 + nt) * 32 + ln) * 2 + r] = word;
            }
        }
        {
            const float* rcin = rc + ((size_t)bk * C_ + j0) * E_;
            #pragma unroll
            for (int it = 0; it < 4; it++) {
                int idx = it * 256 + t;
                int r  = idx >> 4;
                int e0 = (idx & 15) * 4;
                float4 v = *(const float4*)&rcin[(size_t)r * E_ + e0];
                int mt = r >> 4, kt = e0 >> 4;
                int reg = ((r >> 3) & 1) | (((e0 >> 3) & 1) << 1);
                int lp  = (r & 7) * 4 + ((e0 & 7) >> 1);
                uint2 w;
                w.x = pack_h2(v.x, v.y);
                w.y = pack_h2(v.z, v.w);
                *(uint2*)(smem + INF + (mt * 4 + kt) * TILES + reg * REGS + lp * 4) = w;
            }
        }
        __syncthreads();

        // ---- Layer 1 ----
        {
            float d[2][4][4];
            const float* Pp = P_scratch + (size_t)(b * C_ + j0) * H_;
            #pragma unroll
            for (int mtl = 0; mtl < 2; mtl++) {
                int r0 = wm * 32 + mtl * 16 + (lane >> 2);
                #pragma unroll
                for (int ntl = 0; ntl < 4; ntl++) {
                    int col = wn * 32 + ntl * 8 + (lane & 3) * 2;
                    float2 p0 = *(const float2*)&Pp[(size_t)r0 * H_ + col];
                    float2 p1 = *(const float2*)&Pp[(size_t)(r0 + 8) * H_ + col];
                    d[mtl][ntl][0] = p0.x; d[mtl][ntl][1] = p0.y;
                    d[mtl][ntl][2] = p1.x; d[mtl][ntl][3] = p1.y;
                }
            }
            #pragma unroll
            for (int kt = 0; kt < 4; kt++) {
                uint32_t a[2][4];
                #pragma unroll
                for (int mtl = 0; mtl < 2; mtl++) {
                    const char* base = smem + INF + ((wm * 2 + mtl) * 4 + kt) * TILES + lane * 4;
                    a[mtl][0] = *(const uint32_t*)(base);
                    a[mtl][1] = *(const uint32_t*)(base + REGS);
                    a[mtl][2] = *(const uint32_t*)(base + 2 * REGS);
                    a[mtl][3] = *(const uint32_t*)(base + 3 * REGS);
                }
                #pragma unroll
                for (int ntl = 0; ntl < 4; ntl++) {
                    int nt = wn * 4 + ntl;
                    uint2 bv = *(const uint2*)(smem + W1F + ((kt * 16 + nt) * 32 + lane) * 8);
                    uint32_t bw[2] = {bv.x, bv.y};
                    #pragma unroll
                    for (int mtl = 0; mtl < 2; mtl++) mma_f16(d[mtl][ntl], a[mtl], bw);
                }
            }
            #pragma unroll
            for (int mtl = 0; mtl < 2; mtl++) {
                int mt2 = wm * 2 + mtl;
                int lp  = (lane >> 2) * 4 + (lane & 3);
                #pragma unroll
                for (int ntl = 0; ntl < 4; ntl++) {
                    int kt2 = wn * 2 + (ntl >> 1);
                    int rlo = (ntl & 1) * 2;
                    const char* fb = smem + H1F + (mt2 * 8 + kt2) * TILES + lp * 4;
                    *(uint32_t*)(fb + rlo * REGS) =
                        pack_h2(fmaxf(d[mtl][ntl][0], 0.0f), fmaxf(d[mtl][ntl][1], 0.0f));
                    *(uint32_t*)(fb + (rlo + 1) * REGS) =
                        pack_h2(fmaxf(d[mtl][ntl][2], 0.0f), fmaxf(d[mtl][ntl][3], 0.0f));
                }
            }
        }
        __syncthreads();

        // ---- Layer 2 ----
        {
            float d[2][4][4];
            #pragma unroll
            for (int mtl = 0; mtl < 2; mtl++)
                #pragma unroll
                for (int ntl = 0; ntl < 4; ntl++) {
                    int col = wn * 32 + ntl * 8 + (lane & 3) * 2;
                    float2 bb = *(const float2*)(smem + B2S + col * 4);
                    d[mtl][ntl][0] = bb.x; d[mtl][ntl][1] = bb.y;
                    d[mtl][ntl][2] = bb.x; d[mtl][ntl][3] = bb.y;
                }
            #pragma unroll
            for (int kt = 0; kt < 8; kt++) {
                uint32_t a[2][4];
                #pragma unroll
                for (int mtl = 0; mtl < 2; mtl++) {
                    const char* base = smem + H1F + ((wm * 2 + mtl) * 8 + kt) * TILES + lane * 4;
                    a[mtl][0] = *(const uint32_t*)(base);
                    a[mtl][1] = *(const uint32_t*)(base + REGS);
                    a[mtl][2] = *(const uint32_t*)(base + 2 * REGS);
                    a[mtl][3] = *(const uint32_t*)(base + 3 * REGS);
                }
                #pragma unroll
                for (int ntl = 0; ntl < 4; ntl++) {
                    int nt = wn * 4 + ntl;
                    uint2 bv = *(const uint2*)(smem + W2F + ((kt * 16 + nt) * 32 + lane) * 8);
                    uint32_t bw[2] = {bv.x, bv.y};
                    #pragma unroll
                    for (int mtl = 0; mtl < 2; mtl++) mma_f16(d[mtl][ntl], a[mtl], bw);
                }
            }
            #pragma unroll
            for (int mtl = 0; mtl < 2; mtl++) {
                int mt2 = wm * 2 + mtl;
                int lp  = (lane >> 2) * 4 + (lane & 3);
                #pragma unroll
                for (int ntl = 0; ntl < 4; ntl++) {
                    int kt2 = wn * 2 + (ntl >> 1);
                    int rlo = (ntl & 1) * 2;
                    const char* fb = smem + H2F + (mt2 * 8 + kt2) * TILES + lp * 4;
                    *(uint32_t*)(fb + rlo * REGS) =
                        pack_h2(fmaxf(d[mtl][ntl][0], 0.0f), fmaxf(d[mtl][ntl][1], 0.0f));
                    *(uint32_t*)(fb + (rlo + 1) * REGS) =
                        pack_h2(fmaxf(d[mtl][ntl][2], 0.0f), fmaxf(d[mtl][ntl][3], 0.0f));
                }
            }
        }
        __syncthreads();

        // ---- Layer 3 ----
        {
            float d[2][2][4];
            #pragma unroll
            for (int mtl = 0; mtl < 2; mtl++)
                #pragma unroll
                for (int ntl = 0; ntl < 2; ntl++) {
                    int e = wn * 16 + ntl * 8 + (lane & 3) * 2;
                    float2 bb = *(const float2*)(smem + B3S + e * 4);
                    d[mtl][ntl][0] = bb.x; d[mtl][ntl][1] = bb.y;
                    d[mtl][ntl][2] = bb.x; d[mtl][ntl][3] = bb.y;
                }
            #pragma unroll
            for (int kt = 0; kt < 8; kt++) {
                uint32_t a[2][4];
                #pragma unroll
                for (int mtl = 0; mtl < 2; mtl++) {
                    const char* base = smem + H2F + ((wm * 2 + mtl) * 8 + kt) * TILES + lane * 4;
                    a[mtl][0] = *(const uint32_t*)(base);
                    a[mtl][1] = *(const uint32_t*)(base + REGS);
                    a[mtl][2] = *(const uint32_t*)(base + 2 * REGS);
                    a[mtl][3] = *(const uint32_t*)(base + 3 * REGS);
                }
                #pragma unroll
                for (int ntl = 0; ntl < 2; ntl++) {
                    int nt = wn * 2 + ntl;
                    uint2 bv = *(const uint2*)(smem + W3F + ((kt * 8 + nt) * 32 + lane) * 8);
                    uint32_t bw[2] = {bv.x, bv.y};
                    #pragma unroll
                    for (int mtl = 0; mtl < 2; mtl++) mma_f16(d[mtl][ntl], a[mtl], bw);
                }
            }
            #pragma unroll
            for (int mtl = 0; mtl < 2; mtl++) {
                int row = wm * 32 + mtl * 16 + (lane >> 2);
                #pragma unroll
                for (int ntl = 0; ntl < 2; ntl++) {
                    int e = wn * 16 + ntl * 8 + (lane & 3) * 2;
                    *(uint32_t*)(smem + BOUNCE + row * ROWB + e * 2) =
                        pack_h2(d[mtl][ntl][0], d[mtl][ntl][1]);
                    *(uint32_t*)(smem + BOUNCE + (row + 8) * ROWB + e * 2) =
                        pack_h2(d[mtl][ntl][2], d[mtl][ntl][3]);
                }
            }
        }
        __syncthreads();

        prev_bk = bk; prev_j0 = j0;
    }

    if (prev_bk >= 0) {
        uint32_t* Ub = U_scratch + (size_t)prev_bk * 8192;
        #pragma unroll
        for (int w = 0; w < 8; w++) {
            int idx = w * 256 + t;
            int r   = idx & 1;
            int ln  = (idx >> 1) & 31;
            int nt  = (idx >> 6) & 7;
            int ktl = (idx >> 9) & 3;
            int jl  = ktl * 16 + (ln & 3) * 2 + r * 8;
            int e   = nt * 8 + (ln >> 2);
            uint16_t h0 = *(const uint16_t*)(smem + BOUNCE + jl * ROWB + e * 2);
            uint16_t h1 = *(const uint16_t*)(smem + BOUNCE + (jl + 1) * ROWB + e * 2);
            uint32_t word = (uint32_t)h0 | ((uint32_t)h1 << 16);
            int ktg = (prev_j0 >> 4) + ktl;
            Ub[((ktg * 8 + nt) * 32 + ln) * 2 + r] = word;
        }
    }
}

// ---------------------------------------------------------------------------
// Kernel 3: fp16 mma attention, warp grid (Wm2, Wn2, Wk2).
// K-split-2 reduction bounced through the dead current-k B buffer.
// ---------------------------------------------------------------------------
#define AT_A  0
#define AT_B0 34816
#define AT_B1 67584
#define AT_SMEM 100352

__global__ void __launch_bounds__(256, 2)
attn_mma_kernel(const float* __restrict__ rc, const float* __restrict__ rq,
                const float* __restrict__ attc, const float* __restrict__ attq,
                float* __restrict__ out) {
    extern __shared__ char smem[];
    const uint32_t smem_base = smem_u32(smem);
    const int t = threadIdx.x;
    const int x = blockIdx.x;
    const int kg  = x & 31;            // 32 groups of 8 k
    const int Mq  = (x >> 5) & 3;
    const int map = (x >> 7) & 1;
    const int b   = x >> 8;

    const int wid  = t >> 5;
    const int lane = t & 31;
    const int wk = wid >> 2;           // K-split half
    const int wm = (wid >> 1) & 1;     // 2 M-groups of 32 rows
    const int wn = wid & 1;            // 2 N-groups of 32 cols

    const int k0 = kg * 8;

    // ---- Kick off B stage for k0 into buf0 (async, 32KB) ----
    {
        const char* src = (const char*)(U_scratch + ((size_t)(b * C_ + k0)) * 8192);
        #pragma unroll
        for (int it = 0; it < 8; it++) {
            int o = (it * 256 + t) * 16;
            cp_async16(smem_base + AT_B0 + o, src + o);
        }
        cp_commit();
    }

    // ---- Stage A once: 64 rows x 256 j, fp16 frag-major ----
    {
        const float* att = (map ? attq : attc) + (size_t)b * C_ * C_ + (size_t)(Mq * 64) * C_;
        #pragma unroll 4
        for (int it = 0; it < 16; it++) {
            int idx = it * 256 + t;
            int i  = idx >> 6;
            int j0 = (idx & 63) * 4;
            float4 v = *(const float4*)&att[(size_t)i * C_ + j0];
            int mt = i >> 4, kt = j0 >> 4;
            int reg = ((i >> 3) & 1) | (((j0 >> 3) & 1) << 1);
            int lp  = (i & 7) * 4 + ((j0 & 7) >> 1);
            uint2 w;
            w.x = pack_h2(v.x, v.y);
            w.y = pack_h2(v.z, v.w);
            *(uint2*)(smem + AT_A + (mt * 16 + kt) * TILES + reg * REGS + lp * 4) = w;
        }
    }
    cp_wait0();
    __syncthreads();

    float* outbase = out + (map ? (size_t)B_ * C_ * C_ * E_ : 0);
    const float* residbase = map ? rq : rc;

    uint32_t bufoff = AT_B0;
    #pragma unroll 1
    for (int kk = 0; kk < 8; kk++) {
        const int k = k0 + kk;

        if (kk < 7) {
            const char* src = (const char*)(U_scratch + ((size_t)(b * C_ + k + 1)) * 8192);
            uint32_t dst = smem_base + (bufoff ^ (AT_B0 ^ AT_B1));
            #pragma unroll
            for (int it = 0; it < 8; it++) {
                int o = (it * 256 + t) * 16;
                cp_async16(dst + o, src + o);
            }
            cp_commit();
        }

        // ---- mma mainloop: this warp: M32 x N32, kt in [wk*8, wk*8+8) ----
        float d[2][4][4];
        #pragma unroll
        for (int i0 = 0; i0 < 2; i0++)
            #pragma unroll
            for (int i1 = 0; i1 < 4; i1++)
                #pragma unroll
                for (int i2 = 0; i2 < 4; i2++) d[i0][i1][i2] = 0.0f;

        #pragma unroll
        for (int kt8 = 0; kt8 < 8; kt8++) {
            const int kt = wk * 8 + kt8;
            uint32_t a[2][4];
            #pragma unroll
            for (int mtl = 0; mtl < 2; mtl++) {
                const char* base = smem + AT_A + ((wm * 2 + mtl) * 16 + kt) * TILES + lane * 4;
                a[mtl][0] = *(const uint32_t*)(base);
                a[mtl][1] = *(const uint32_t*)(base + REGS);
                a[mtl][2] = *(const uint32_t*)(base + 2 * REGS);
                a[mtl][3] = *(const uint32_t*)(base + 3 * REGS);
            }
            uint32_t bw[4][2];
            #pragma unroll
            for (int ntl = 0; ntl < 4; ntl++) {
                int nt = wn * 4 + ntl;
                uint2 bv = *(const uint2*)(smem + bufoff + ((kt * 8 + nt) * 32 + lane) * 8);
                bw[ntl][0] = bv.x; bw[ntl][1] = bv.y;
            }
            #pragma unroll
            for (int mtl = 0; mtl < 2; mtl++)
                #pragma unroll
                for (int ntl = 0; ntl < 4; ntl++)
                    mma_f16(d[mtl][ntl], a[mtl], bw[ntl]);
        }

        __syncthreads();   // all mainloop reads of B[cur] complete

        // ---- K-split reduction through dead B[cur] buffer ----
        if (wk == 1) {
            char* scr = smem + bufoff + (wid & 3) * 4096;
            #pragma unroll
            for (int mtl = 0; mtl < 2; mtl++)
                #pragma unroll
                for (int ntl = 0; ntl < 4; ntl++)
                    #pragma unroll
                    for (int q = 0; q < 4; q++) {
                        int idx = (mtl * 4 + ntl) * 4 + q;
                        *(float*)(scr + idx * 128 + lane * 4) = d[mtl][ntl][q];
                    }
        }
        __syncthreads();

        if (wk == 0) {
            const char* scr = smem + bufoff + (wid & 3) * 4096;
            #pragma unroll
            for (int mtl = 0; mtl < 2; mtl++)
                #pragma unroll
                for (int ntl = 0; ntl < 4; ntl++)
                    #pragma unroll
                    for (int q = 0; q < 4; q++) {
                        int idx = (mtl * 4 + ntl) * 4 + q;
                        d[mtl][ntl][q] += *(const float*)(scr + idx * 128 + lane * 4);
                    }

            // ---- epilogue: out = resid - ALPHA * D (fp32), M32 x N32 tile ----
            const float* resid = residbase + ((size_t)(b * C_ + k) * C_) * E_;
            float* o = outbase + ((size_t)(b * C_ + k) * C_) * E_;
            #pragma unroll
            for (int mtl = 0; mtl < 2; mtl++) {
                int row = Mq * 64 + wm * 32 + mtl * 16 + (lane >> 2);
                #pragma unroll
                for (int ntl = 0; ntl < 4; ntl++) {
                    int e = wn * 32 + ntl * 8 + (lane & 3) * 2;
                    float2 rA = *(const float2*)&resid[(size_t)row * E_ + e];
                    float2 rB = *(const float2*)&resid[(size_t)(row + 8) * E_ + e];
                    float2 oA, oB;
                    oA.x = rA.x - ALPHA * d[mtl][ntl][0];
                    oA.y = rA.y - ALPHA * d[mtl][ntl][1];
                    oB.x = rB.x - ALPHA * d[mtl][ntl][2];
                    oB.y = rB.y - ALPHA * d[mtl][ntl][3];
                    *(float2*)&o[(size_t)row * E_ + e]       = oA;
                    *(float2*)&o[(size_t)(row + 8) * E_ + e] = oB;
                }
            }
        }

        if (kk < 7) {
            cp_wait0();
            __syncthreads();
            bufoff ^= (AT_B0 ^ AT_B1);
        }
    }
}

// ---------------------------------------------------------------------------
// Launch
// ---------------------------------------------------------------------------
extern "C" void kernel_launch(void* const* d_in, const int* in_sizes, int n_in,
                              void* d_out, int out_size) {
    const float* x    = (const float*)d_in[0];
    const float* y    = (const float*)d_in[1];
    const float* rc   = (const float*)d_in[2];
    const float* rq   = (const float*)d_in[3];
    const float* attc = (const float*)d_in[4];
    const float* attq = (const float*)d_in[5];
    const float* W1   = (const float*)d_in[6];
    const float* b1   = (const float*)d_in[7];
    const float* W2   = (const float*)d_in[8];
    const float* b2   = (const float*)d_in[9];
    const float* W3   = (const float*)d_in[10];
    const float* b3   = (const float*)d_in[11];
    float* out = (float*)d_out;

    cudaFuncSetAttribute(mlp_tc_kernel,   cudaFuncAttributeMaxDynamicSharedMemorySize, MLP_SMEM_B);
    cudaFuncSetAttribute(attn_mma_kernel, cudaFuncAttributeMaxDynamicSharedMemorySize, AT_SMEM);

    p_kernel<<<B_ * C_, H_>>>(x, y, W1, b1);
    mlp_tc_kernel<<<296, 256, MLP_SMEM_B>>>(rc, W1, b2, W2, W3, b3);
    attn_mma_kernel<<<1024, 256, AT_SMEM>>>(rc, rq, attc, attq, out);
}